// round 16
// baseline (speedup 1.0000x reference)
#include <cuda_runtime.h>
#include <cuda_bf16.h>
#include <cstdint>
#include <cstring>

// NanEuclidean: X[4096,1024] f32, Y[4096,1024] f32 (10% NaN) -> out[4096,4096] f32
//   d = sqrt( clip(XX.pY - 2 Xc.Yc + pX.YY, 0) / max(1, pX.pY) * 1024 ), NaN where pc==0
//
// R16 = R15 (2 CTAs/SM, 128x64 tile, derived squares) with the PC GEMM replaced by
//       integer AND+POPC over presence bitmasks (exact). Tensor work -25%.

#define NKB    32            // K chunks of 32 per tile
#define TILE8K 8192u         // one 128-row x 64-byte swizzled tile image
#define PLANEB 24576u        // A planes 2x8K + B half-planes 2x4K
#define STAGEB 25600u        // planes + Amask 512B + Bmask 256B (+pad), 1KB-aligned
#define NSTAGE 4
#define GSMEM  (NSTAGE * STAGEB + 1024u)

// 16 MB each: [row_block(32)][comp(2)][k_block(32)] 8KB tiles
__device__ __align__(1024) __nv_bfloat16 g_nanEuc_A[8388608ull];
__device__ __align__(1024) __nv_bfloat16 g_nanEuc_B[8388608ull];
// presence bitmasks: [rb(32)][kb(32)][row(128)] one u32 (bit k = k-th of 32)
__device__ __align__(1024) uint32_t g_maskA[131072];
__device__ __align__(1024) uint32_t g_maskB[131072];

// ---------------- helpers ----------------
__device__ __forceinline__ uint32_t bf2_u32(__nv_bfloat162 v) {
    uint32_t u; memcpy(&u, &v, 4); return u;
}
__device__ __forceinline__ uint32_t smem_u32(const void* p) {
    uint32_t a;
    asm("{ .reg .u64 t; cvta.to.shared.u64 t, %1; cvt.u32.u64 %0, t; }" : "=r"(a) : "l"(p));
    return a;
}
__device__ __forceinline__ void cpasync16(uint32_t dst, const void* src) {
    asm volatile("cp.async.cg.shared.global [%0], [%1], 16;" :: "r"(dst), "l"(src) : "memory");
}
__device__ __forceinline__ uint32_t bmul2(uint32_t a, uint32_t b) {
    uint32_t d;
    asm("mul.rn.bf16x2 %0, %1, %2;" : "=r"(d) : "r"(a), "r"(b));
    return d;
}
#define LDSM4(r0, r1, r2, r3, addr) \
    asm volatile("ldmatrix.sync.aligned.m8n8.x4.shared.b16 {%0,%1,%2,%3}, [%4];" \
        : "=r"(r0), "=r"(r1), "=r"(r2), "=r"(r3) : "r"(addr))

__device__ __forceinline__ void mma16816(float* c, const uint32_t* a, const uint32_t* b) {
    asm volatile(
        "mma.sync.aligned.m16n8k16.row.col.f32.bf16.bf16.f32 "
        "{%0,%1,%2,%3}, {%4,%5,%6,%7}, {%8,%9}, {%0,%1,%2,%3};"
        : "+f"(c[0]), "+f"(c[1]), "+f"(c[2]), "+f"(c[3])
        : "r"(a[0]), "r"(a[1]), "r"(a[2]), "r"(a[3]), "r"(b[0]), "r"(b[1]));
}
__device__ __forceinline__ bool nan_bits(float x) {
    return (__float_as_uint(x) & 0x7fffffffu) > 0x7f800000u;  // fast-math safe
}

// ---------------- Kernel 1: component tiles + presence bitmask bytes ----------------
// A comps (from X): [-2Xc, pX].  B comps (from Y): [Yc, pY].
// Tile: 128 rows x 64B (32 bf16). 16B seg s stored at local seg s ^ ((r>>1)&3).
__global__ void __launch_bounds__(256) nanEuc_prep(const float* __restrict__ X,
                                                   const float* __restrict__ Y) {
    const int is_b   = (int)(blockIdx.x >> 11);       // 2048 blocks per matrix
    const float* src = is_b ? Y : X;
    unsigned idx = (blockIdx.x & 2047u) * 256u + threadIdx.x;  // 0..524287
    unsigned s   = idx & 3u;              // 16B seg within 64B (8 k-values)
    unsigned kb  = (idx >> 2) & 31u;      // k block of 32
    unsigned row = idx >> 7;              // 0..4095

    const float4 v0 = *reinterpret_cast<const float4*>(src + (size_t)row * 1024u + kb * 32u + s * 8u);
    const float4 v1 = *reinterpret_cast<const float4*>(src + (size_t)row * 1024u + kb * 32u + s * 8u + 4u);
    float x[8] = {v0.x, v0.y, v0.z, v0.w, v1.x, v1.y, v1.z, v1.w};

    uint32_t c0[4], c1[4];                // 4 bf16x2 per comp
    unsigned mbyte = 0;                   // presence bits for this thread's 8 k-values
    #pragma unroll
    for (int i = 0; i < 4; i++) {
        float e0 = x[2 * i], e1 = x[2 * i + 1];
        bool  m0 = nan_bits(e0), m1 = nan_bits(e1);
        float a0 = m0 ? 0.f : e0, a1 = m1 ? 0.f : e1;
        float p0 = m0 ? 0.f : 1.f, p1 = m1 ? 0.f : 1.f;
        float f0 = is_b ? a0 : -2.f * a0;
        float f1 = is_b ? a1 : -2.f * a1;
        c0[i] = bf2_u32(__floats2bfloat162_rn(f0, f1));   // A: -2Xc   B: Yc
        c1[i] = bf2_u32(__floats2bfloat162_rn(p0, p1));   // presence
        mbyte |= (m0 ? 0u : 1u) << (2 * i);
        mbyte |= (m1 ? 0u : 1u) << (2 * i + 1);
    }

    unsigned rb = row >> 7, r = row & 127u;
    unsigned off = r * 64u + ((s ^ ((r >> 1) & 3u)) << 4);   // swizzled 16B slot
    char* dst = reinterpret_cast<char*>(is_b ? g_nanEuc_B : g_nanEuc_A);
    size_t tb = ((size_t)rb * 64u + kb) * 8192u;             // [rb][comp][kb]; comp stride 32*8192
    *reinterpret_cast<uint4*>(dst + tb +           off) = make_uint4(c0[0], c0[1], c0[2], c0[3]);
    *reinterpret_cast<uint4*>(dst + tb + 262144u + off) = make_uint4(c1[0], c1[1], c1[2], c1[3]);

    // presence bitmask byte: word (rb,kb,r), byte s  -> bit k = s*8 + j
    char* gm = reinterpret_cast<char*>(is_b ? g_maskB : g_maskA);
    gm[(((size_t)rb * 32u + kb) * 128u + r) * 4u + s] = (char)mbyte;
}

// ---------------- Kernel 2: mma.sync GEMM (D) + popc (PC), 2 CTAs/SM ----------------
// 256 threads = 8 warps in 4x2; warp tile 32x32; CTA tile 128x64.
__global__ void __launch_bounds__(256, 2) nanEuc_gemm(float* __restrict__ out) {
    extern __shared__ char smraw[];
    const uint32_t smbase = (smem_u32(smraw) + 1023u) & ~1023u;
    char* smemc = smraw + (smbase - smem_u32(smraw));   // C alias of smbase

    const int tid = threadIdx.x, lane = tid & 31, w = tid >> 5;
    const int wr = w >> 1, wc = w & 1;            // 4 x 2 warp grid
    const int cb = blockIdx.x, rb = blockIdx.y;   // cb in 0..63 (64-wide tiles)

    const char* Ag = reinterpret_cast<const char*>(g_nanEuc_A);
    const char* Bg = reinterpret_cast<const char*>(g_nanEuc_B);
    const char* Amg = reinterpret_cast<const char*>(g_maskA);
    const char* Bmg = reinterpret_cast<const char*>(g_maskB);
    const uint32_t QUARTER2 = 0x3E803E80u;        // bf16x2 {0.25, 0.25}

    float    accD[2][4][4];
    uint32_t pcacc[2][4][2];   // [mi][ni][q>>1]: low16 = even col, high16 = odd col
    #pragma unroll
    for (int mi = 0; mi < 2; mi++)
        #pragma unroll
        for (int ni = 0; ni < 4; ni++) {
            #pragma unroll
            for (int q = 0; q < 4; q++) accD[mi][ni][q] = 0.f;
            pcacc[mi][ni][0] = 0u; pcacc[mi][ni][1] = 0u;
        }

    // ldmatrix lane addressing (64B rows, seg swizzle s^((row>>1)&3))
    const uint32_t hiA = (uint32_t)(lane >> 4);
    const uint32_t hiB = (uint32_t)((lane >> 3) & 1);
    uint32_t rtermA[2], xorA[2], rtermB[2], xorB[2];
    #pragma unroll
    for (int mi = 0; mi < 2; mi++) {
        uint32_t rowA = wr * 32 + mi * 16 + (lane & 15);
        rtermA[mi] = rowA * 64u;  xorA[mi] = (rowA >> 1) & 3u;
    }
    #pragma unroll
    for (int nt = 0; nt < 2; nt++) {
        uint32_t rowB = wc * 32 + nt * 16 + (lane & 7) + ((lane >> 4) & 1) * 8;  // local 0..63
        rtermB[nt] = rowB * 64u;  xorB[nt] = (rowB >> 1) & 3u;
    }
    const int rl = wr * 32 + (lane >> 2);       // popc row base (CTA-local)
    const int cl = wc * 32 + (lane & 3) * 2;    // popc col base (CTA-local, 0..63)

    // stage: [A s 8K][A pX 8K][B Yc 4K][B pY 4K][Amask 512B][Bmask 256B]
    const uint32_t bhalf = (uint32_t)(cb & 1) * 4096u;
    const uint32_t bmrow = (uint32_t)(cb & 1) * 64u;
    auto load_stage = [&](int slot, int c) {
        const uint32_t dst0 = smbase + (uint32_t)slot * STAGEB;
        for (int i = tid; i < 1584; i += 256) {
            const char* src;
            if (i < 1024) {
                int comp = i >> 9;
                src = Ag + ((size_t)(rb * 2 + comp) * NKB + c) * TILE8K + (size_t)(i & 511) * 16u;
            } else if (i < 1536) {
                int j = i - 1024;
                int comp = j >> 8;
                src = Bg + ((size_t)((cb >> 1) * 2 + comp) * NKB + c) * TILE8K
                    + bhalf + (size_t)(j & 255) * 16u;
            } else if (i < 1568) {
                int j = i - 1536;   // 0..31: 512B of A masks (128 rows)
                src = Amg + ((size_t)rb * 32u + c) * 512u + (size_t)j * 16u;
            } else {
                int j = i - 1568;   // 0..15: 256B of B masks (64 rows of this half)
                src = Bmg + (((size_t)(cb >> 1) * 32u + c) * 128u + bmrow) * 4u + (size_t)j * 16u;
            }
            cpasync16(dst0 + (uint32_t)i * 16u, src);
        }
    };

    // prologue: 3 stages in flight
    #pragma unroll
    for (int c = 0; c < NSTAGE - 1; c++) {
        load_stage(c, c);
        asm volatile("cp.async.commit_group;" ::: "memory");
    }

    int slot = 0;
    for (int c = 0; c < NKB; c++) {
        asm volatile("cp.async.wait_group %0;" :: "n"(NSTAGE - 2) : "memory");
        __syncthreads();
        if (c + NSTAGE - 1 < NKB) {
            int ns = slot + NSTAGE - 1; if (ns >= NSTAGE) ns -= NSTAGE;
            load_stage(ns, c + NSTAGE - 1);
        }
        asm volatile("cp.async.commit_group;" ::: "memory");   // empty group keeps count

        const uint32_t base = smbase + (uint32_t)slot * STAGEB;
        const char*    cbase = smemc + (size_t)slot * STAGEB;
        if (++slot == NSTAGE) slot = 0;

        // ---- PC: popc over this chunk's 32 k-bits (ALU pipe; overlaps MMAs) ----
        {
            const uint32_t* amw = (const uint32_t*)(cbase + PLANEB);
            const uint32_t* bmw = (const uint32_t*)(cbase + PLANEB + 512u);
            uint32_t am[4], bm[8];
            #pragma unroll
            for (int r4 = 0; r4 < 4; r4++) am[r4] = amw[rl + r4 * 8];
            #pragma unroll
            for (int ni = 0; ni < 4; ni++) {
                bm[ni * 2]     = bmw[cl + ni * 8];
                bm[ni * 2 + 1] = bmw[cl + ni * 8 + 1];
            }
            #pragma unroll
            for (int mi = 0; mi < 2; mi++)
                #pragma unroll
                for (int ni = 0; ni < 4; ni++)
                    #pragma unroll
                    for (int h = 0; h < 2; h++)
                        pcacc[mi][ni][h] += (uint32_t)__popc(am[mi * 2 + h] & bm[ni * 2])
                                          + ((uint32_t)__popc(am[mi * 2 + h] & bm[ni * 2 + 1]) << 16);
        }

        #pragma unroll
        for (int kk = 0; kk < 2; kk++) {
            const uint32_t sA = (uint32_t)kk * 2u + hiA;
            const uint32_t sB = (uint32_t)kk * 2u + hiB;
            uint32_t a[2][4], b1[4][2], b2[4][2];

            // ---- comp 1: D += (-2Xc) . Yc^T ----
            #pragma unroll
            for (int mi = 0; mi < 2; mi++)
                LDSM4(a[mi][0], a[mi][1], a[mi][2], a[mi][3],
                      base + 0u * 8192u + rtermA[mi] + ((sA ^ xorA[mi]) << 4));
            #pragma unroll
            for (int nt = 0; nt < 2; nt++)
                LDSM4(b1[2 * nt][0], b1[2 * nt][1], b1[2 * nt + 1][0], b1[2 * nt + 1][1],
                      base + 16384u + rtermB[nt] + ((sB ^ xorB[nt]) << 4));
            #pragma unroll
            for (int mi = 0; mi < 2; mi++)
                #pragma unroll
                for (int ni = 0; ni < 4; ni++) mma16816(accD[mi][ni], a[mi], b1[ni]);

            // ---- comp 0: D += XX . pY^T  (XX = (-2Xc)^2 * 0.25, in-register) ----
            #pragma unroll
            for (int nt = 0; nt < 2; nt++)
                LDSM4(b2[2 * nt][0], b2[2 * nt][1], b2[2 * nt + 1][0], b2[2 * nt + 1][1],
                      base + 20480u + rtermB[nt] + ((sB ^ xorB[nt]) << 4));
            #pragma unroll
            for (int mi = 0; mi < 2; mi++)
                #pragma unroll
                for (int r4 = 0; r4 < 4; r4++)
                    a[mi][r4] = bmul2(bmul2(a[mi][r4], a[mi][r4]), QUARTER2);
            #pragma unroll
            for (int mi = 0; mi < 2; mi++)
                #pragma unroll
                for (int ni = 0; ni < 4; ni++) mma16816(accD[mi][ni], a[mi], b2[ni]);

            // ---- comp 2: D += pX . YY^T  (YY = Yc^2 in-register) ----
            #pragma unroll
            for (int mi = 0; mi < 2; mi++)
                LDSM4(a[mi][0], a[mi][1], a[mi][2], a[mi][3],
                      base + 8192u + rtermA[mi] + ((sA ^ xorA[mi]) << 4));
            #pragma unroll
            for (int ni = 0; ni < 4; ni++) {
                b1[ni][0] = bmul2(b1[ni][0], b1[ni][0]);
                b1[ni][1] = bmul2(b1[ni][1], b1[ni][1]);
            }
            #pragma unroll
            for (int mi = 0; mi < 2; mi++)
                #pragma unroll
                for (int ni = 0; ni < 4; ni++) mma16816(accD[mi][ni], a[mi], b1[ni]);
        }
    }

    // ---- epilogue: r = pc==0 ? NaN : sqrt(max(d,0) * 1024 / pc)  (pc exact) ----
    const int r0 = rb * 128 + wr * 32 + (lane >> 2);
    const int c0 = cb * 64 + wc * 32 + (lane & 3) * 2;
    #pragma unroll
    for (int mi = 0; mi < 2; mi++)
        #pragma unroll
        for (int ni = 0; ni < 4; ni++) {
            const int rr = r0 + mi * 16;
            const int cc = c0 + ni * 8;
            float v[4];
            #pragma unroll
            for (int q = 0; q < 4; q++) {
                float d = accD[mi][ni][q];
                uint32_t pi = (pcacc[mi][ni][q >> 1] >> ((q & 1) * 16)) & 0xffffu;
                v[q] = (pi == 0u) ? __int_as_float(0x7fc00000)
                                  : sqrtf(fmaxf(d, 0.f) * 1024.f / (float)pi);
            }
            *reinterpret_cast<float2*>(out + (size_t)rr * 4096u + cc)       = make_float2(v[0], v[1]);
            *reinterpret_cast<float2*>(out + (size_t)(rr + 8) * 4096u + cc) = make_float2(v[2], v[3]);
        }
}

// ---------------- launch ----------------
extern "C" void kernel_launch(void* const* d_in, const int* in_sizes, int n_in,
                              void* d_out, int out_size) {
    (void)in_sizes; (void)n_in; (void)out_size;
    const float* X = (const float*)d_in[0];
    const float* Y = (const float*)d_in[1];
    float* out = (float*)d_out;

    nanEuc_prep<<<4096, 256>>>(X, Y);

    cudaFuncSetAttribute(nanEuc_gemm, cudaFuncAttributeMaxDynamicSharedMemorySize, GSMEM);
    nanEuc_gemm<<<dim3(64, 32, 1), 256, GSMEM>>>(out);
}

// round 17
// speedup vs baseline: 1.2470x; 1.2470x over previous
#include <cuda_runtime.h>
#include <cuda_bf16.h>
#include <cstdint>
#include <cstring>

// NanEuclidean: X[4096,1024] f32, Y[4096,1024] f32 (10% NaN) -> out[4096,4096] f32
//   d = sqrt( clip(XX.pY - 2 Xc.Yc + pX.YY, 0) / max(1, pX.pY) * 1024 ), NaN where pc==0
//
// R17 = R15 (2 CTAs/SM, 128x64 tile, 4 GEMMs on tensor pipe) storing ONLY
//       A = -2Xc and B = Yc. pX/pY derived via set.ne.bf16x2 (exact: missing -> +-0,
//       real values never round to bf16 0), XX/YY derived via mul.rn.bf16x2.
//       Stage 12KB, 8-stage pipeline: smem traffic -50%, tensor pipe sole binder.

#define NKB    32            // K chunks of 32 per tile
#define TILE8K 8192u         // one 128-row x 64-byte swizzled tile image
#define STAGEB 12288u        // A plane 8K + B half-plane 4K
#define NSTAGE 8
#define GSMEM  (NSTAGE * STAGEB + 1024u)

// 8 MB each: [row_block(32)][k_block(32)] 8KB tiles
__device__ __align__(1024) __nv_bfloat16 g_nanEuc_A[4194304ull];
__device__ __align__(1024) __nv_bfloat16 g_nanEuc_B[4194304ull];

// ---------------- helpers ----------------
__device__ __forceinline__ uint32_t bf2_u32(__nv_bfloat162 v) {
    uint32_t u; memcpy(&u, &v, 4); return u;
}
__device__ __forceinline__ uint32_t smem_u32(const void* p) {
    uint32_t a;
    asm("{ .reg .u64 t; cvta.to.shared.u64 t, %1; cvt.u32.u64 %0, t; }" : "=r"(a) : "l"(p));
    return a;
}
__device__ __forceinline__ void cpasync16(uint32_t dst, const void* src) {
    asm volatile("cp.async.cg.shared.global [%0], [%1], 16;" :: "r"(dst), "l"(src) : "memory");
}
__device__ __forceinline__ uint32_t bmul2(uint32_t a, uint32_t b) {
    uint32_t d;
    asm("mul.rn.bf16x2 %0, %1, %2;" : "=r"(d) : "r"(a), "r"(b));
    return d;
}
// per-half: (h != 0) ? 1.0bf : 0.0bf   (+-0 -> 0; NaN never present in planes)
__device__ __forceinline__ uint32_t bsetne2(uint32_t a) {
    uint32_t d;
    asm("set.ne.bf16x2.bf16x2 %0, %1, %2;" : "=r"(d) : "r"(a), "r"(0u));
    return d;
}
#define LDSM4(r0, r1, r2, r3, addr) \
    asm volatile("ldmatrix.sync.aligned.m8n8.x4.shared.b16 {%0,%1,%2,%3}, [%4];" \
        : "=r"(r0), "=r"(r1), "=r"(r2), "=r"(r3) : "r"(addr))

__device__ __forceinline__ void mma16816(float* c, const uint32_t* a, const uint32_t* b) {
    asm volatile(
        "mma.sync.aligned.m16n8k16.row.col.f32.bf16.bf16.f32 "
        "{%0,%1,%2,%3}, {%4,%5,%6,%7}, {%8,%9}, {%0,%1,%2,%3};"
        : "+f"(c[0]), "+f"(c[1]), "+f"(c[2]), "+f"(c[3])
        : "r"(a[0]), "r"(a[1]), "r"(a[2]), "r"(a[3]), "r"(b[0]), "r"(b[1]));
}
__device__ __forceinline__ bool nan_bits(float x) {
    return (__float_as_uint(x) & 0x7fffffffu) > 0x7f800000u;  // fast-math safe
}

// ---------------- Kernel 1: single bf16 plane per matrix ----------------
// A (from X): -2Xc.  B (from Y): Yc.  Missing entries stored as 0.
// Tile: 128 rows x 64B (32 bf16). 16B seg s stored at local seg s ^ ((r>>1)&3).
__global__ void __launch_bounds__(256) nanEuc_prep(const float* __restrict__ X,
                                                   const float* __restrict__ Y) {
    const int is_b   = (int)(blockIdx.x >> 11);       // 2048 blocks per matrix
    const float* src = is_b ? Y : X;
    unsigned idx = (blockIdx.x & 2047u) * 256u + threadIdx.x;  // 0..524287
    unsigned s   = idx & 3u;              // 16B seg within 64B (8 k-values)
    unsigned kb  = (idx >> 2) & 31u;      // k block of 32
    unsigned row = idx >> 7;              // 0..4095

    const float4 v0 = *reinterpret_cast<const float4*>(src + (size_t)row * 1024u + kb * 32u + s * 8u);
    const float4 v1 = *reinterpret_cast<const float4*>(src + (size_t)row * 1024u + kb * 32u + s * 8u + 4u);
    float x[8] = {v0.x, v0.y, v0.z, v0.w, v1.x, v1.y, v1.z, v1.w};

    uint32_t c0[4];
    #pragma unroll
    for (int i = 0; i < 4; i++) {
        float e0 = x[2 * i], e1 = x[2 * i + 1];
        float a0 = nan_bits(e0) ? 0.f : e0;
        float a1 = nan_bits(e1) ? 0.f : e1;
        float f0 = is_b ? a0 : -2.f * a0;
        float f1 = is_b ? a1 : -2.f * a1;
        c0[i] = bf2_u32(__floats2bfloat162_rn(f0, f1));
    }

    unsigned rb = row >> 7, r = row & 127u;
    unsigned off = r * 64u + ((s ^ ((r >> 1) & 3u)) << 4);   // swizzled 16B slot
    char* dst = reinterpret_cast<char*>(is_b ? g_nanEuc_B : g_nanEuc_A);
    size_t tb = ((size_t)rb * 32u + kb) * 8192u;
    *reinterpret_cast<uint4*>(dst + tb + off) = make_uint4(c0[0], c0[1], c0[2], c0[3]);
}

// ---------------- Kernel 2: mma.sync GEMM, all planes derived in-register ----------------
// 256 threads = 8 warps in 4x2; warp tile 32x32; CTA tile 128x64. 2 CTAs/SM.
__global__ void __launch_bounds__(256, 2) nanEuc_gemm(float* __restrict__ out) {
    extern __shared__ char smraw[];
    const uint32_t smbase = (smem_u32(smraw) + 1023u) & ~1023u;

    const int tid = threadIdx.x, lane = tid & 31, w = tid >> 5;
    const int wr = w >> 1, wc = w & 1;            // 4 x 2 warp grid
    const int cb = blockIdx.x, rb = blockIdx.y;   // cb in 0..63 (64-wide tiles)

    const char* Ag = reinterpret_cast<const char*>(g_nanEuc_A);
    const char* Bg = reinterpret_cast<const char*>(g_nanEuc_B);
    const uint32_t QUARTER2 = 0x3E803E80u;        // bf16x2 {0.25, 0.25}

    float accD[2][4][4];
    float accP[2][4][4];
    #pragma unroll
    for (int mi = 0; mi < 2; mi++)
        #pragma unroll
        for (int ni = 0; ni < 4; ni++)
            #pragma unroll
            for (int q = 0; q < 4; q++) { accD[mi][ni][q] = 0.f; accP[mi][ni][q] = 0.f; }

    // ldmatrix lane addressing (64B rows, seg swizzle s^((row>>1)&3))
    const uint32_t hiA = (uint32_t)(lane >> 4);
    const uint32_t hiB = (uint32_t)((lane >> 3) & 1);
    uint32_t rtermA[2], xorA[2], rtermB[2], xorB[2];
    #pragma unroll
    for (int mi = 0; mi < 2; mi++) {
        uint32_t rowA = wr * 32 + mi * 16 + (lane & 15);
        rtermA[mi] = rowA * 64u;  xorA[mi] = (rowA >> 1) & 3u;
    }
    #pragma unroll
    for (int nt = 0; nt < 2; nt++) {
        uint32_t rowB = wc * 32 + nt * 16 + (lane & 7) + ((lane >> 4) & 1) * 8;  // local 0..63
        rtermB[nt] = rowB * 64u;  xorB[nt] = (rowB >> 1) & 3u;
    }

    // stage layout: [A plane 8K][B half-plane 4K]
    const uint32_t bhalf = (uint32_t)(cb & 1) * 4096u;
    auto load_stage = [&](int slot, int c) {
        const uint32_t dst0 = smbase + (uint32_t)slot * STAGEB;
        #pragma unroll
        for (int i = tid; i < (int)(STAGEB / 16u); i += 256) {
            const char* src;
            if (i < 512) {
                src = Ag + ((size_t)rb * 32u + c) * TILE8K + (size_t)i * 16u;
            } else {
                int j = i - 512;   // 0..255
                src = Bg + ((size_t)(cb >> 1) * 32u + c) * TILE8K + bhalf + (size_t)j * 16u;
            }
            cpasync16(dst0 + (uint32_t)i * 16u, src);
        }
    };

    // prologue: 7 stages in flight
    #pragma unroll
    for (int c = 0; c < NSTAGE - 1; c++) {
        load_stage(c, c);
        asm volatile("cp.async.commit_group;" ::: "memory");
    }

    for (int c = 0; c < NKB; c++) {
        asm volatile("cp.async.wait_group %0;" :: "n"(NSTAGE - 2) : "memory");
        __syncthreads();
        if (c + NSTAGE - 1 < NKB) load_stage((c + NSTAGE - 1) & (NSTAGE - 1), c + NSTAGE - 1);
        asm volatile("cp.async.commit_group;" ::: "memory");   // empty group keeps count

        const uint32_t base = smbase + (uint32_t)(c & (NSTAGE - 1)) * STAGEB;

        #pragma unroll
        for (int kk = 0; kk < 2; kk++) {
            const uint32_t sA = (uint32_t)kk * 2u + hiA;
            const uint32_t sB = (uint32_t)kk * 2u + hiB;
            uint32_t a[2][4], aP[2][4], b1[4][2], b2[4][2];

            // ---- load s = -2Xc and Yc ----
            #pragma unroll
            for (int mi = 0; mi < 2; mi++)
                LDSM4(a[mi][0], a[mi][1], a[mi][2], a[mi][3],
                      base + rtermA[mi] + ((sA ^ xorA[mi]) << 4));
            #pragma unroll
            for (int nt = 0; nt < 2; nt++)
                LDSM4(b1[2 * nt][0], b1[2 * nt][1], b1[2 * nt + 1][0], b1[2 * nt + 1][1],
                      base + 8192u + rtermB[nt] + ((sB ^ xorB[nt]) << 4));

            // ---- comp 1: D += (-2Xc) . Yc^T ----
            #pragma unroll
            for (int mi = 0; mi < 2; mi++)
                #pragma unroll
                for (int ni = 0; ni < 4; ni++) mma16816(accD[mi][ni], a[mi], b1[ni]);

            // ---- derive presence planes (exact): pX = (s != 0), pY = (Yc != 0) ----
            #pragma unroll
            for (int mi = 0; mi < 2; mi++)
                #pragma unroll
                for (int r4 = 0; r4 < 4; r4++) aP[mi][r4] = bsetne2(a[mi][r4]);
            #pragma unroll
            for (int ni = 0; ni < 4; ni++) {
                b2[ni][0] = bsetne2(b1[ni][0]);
                b2[ni][1] = bsetne2(b1[ni][1]);
            }

            // ---- comp 0: D += XX . pY^T  (XX = s^2 * 0.25, in-register) ----
            #pragma unroll
            for (int mi = 0; mi < 2; mi++)
                #pragma unroll
                for (int r4 = 0; r4 < 4; r4++)
                    a[mi][r4] = bmul2(bmul2(a[mi][r4], a[mi][r4]), QUARTER2);
            #pragma unroll
            for (int mi = 0; mi < 2; mi++)
                #pragma unroll
                for (int ni = 0; ni < 4; ni++) mma16816(accD[mi][ni], a[mi], b2[ni]);

            // ---- comp 2: D += pX . YY^T  (YY = Yc^2 in-register) ----
            #pragma unroll
            for (int ni = 0; ni < 4; ni++) {
                b1[ni][0] = bmul2(b1[ni][0], b1[ni][0]);
                b1[ni][1] = bmul2(b1[ni][1], b1[ni][1]);
            }
            #pragma unroll
            for (int mi = 0; mi < 2; mi++)
                #pragma unroll
                for (int ni = 0; ni < 4; ni++) {
                    mma16816(accD[mi][ni], aP[mi], b1[ni]);
                    mma16816(accP[mi][ni], aP[mi], b2[ni]);   // PC += pX . pY^T
                }
        }
    }

    // ---- epilogue: r = pc==0 ? NaN : sqrt(max(d,0) * 1024 / max(pc,1)) ----
    const int r0 = rb * 128 + wr * 32 + (lane >> 2);
    const int c0 = cb * 64 + wc * 32 + (lane & 3) * 2;
    #pragma unroll
    for (int mi = 0; mi < 2; mi++)
        #pragma unroll
        for (int ni = 0; ni < 4; ni++) {
            const int rr = r0 + mi * 16;
            const int cc = c0 + ni * 8;
            float v[4];
            #pragma unroll
            for (int q = 0; q < 4; q++) {
                float d = accD[mi][ni][q], p = accP[mi][ni][q];
                v[q] = (p == 0.f) ? __int_as_float(0x7fc00000)
                                  : sqrtf(fmaxf(d, 0.f) * 1024.f / fmaxf(p, 1.f));
            }
            *reinterpret_cast<float2*>(out + (size_t)rr * 4096u + cc)       = make_float2(v[0], v[1]);
            *reinterpret_cast<float2*>(out + (size_t)(rr + 8) * 4096u + cc) = make_float2(v[2], v[3]);
        }
}

// ---------------- launch ----------------
extern "C" void kernel_launch(void* const* d_in, const int* in_sizes, int n_in,
                              void* d_out, int out_size) {
    (void)in_sizes; (void)n_in; (void)out_size;
    const float* X = (const float*)d_in[0];
    const float* Y = (const float*)d_in[1];
    float* out = (float*)d_out;

    nanEuc_prep<<<4096, 256>>>(X, Y);

    cudaFuncSetAttribute(nanEuc_gemm, cudaFuncAttributeMaxDynamicSharedMemorySize, GSMEM);
    nanEuc_gemm<<<dim3(64, 32, 1), 256, GSMEM>>>(out);
}